// round 12
// baseline (speedup 1.0000x reference)
#include <cuda_runtime.h>
#include <math.h>
#include <stdint.h>

#define BB 2
#define CC 128
#define HH 256      // 2*C
#define SS 4096     // 64*64 tokens
#define NH 4
#define DD 32       // head dim

#define QS 0.1767766952966369f   // 1/sqrt(32)
#define QS2 (QS * 1.4426950408889634f)   // fold log2(e) for ex2-domain softmax

// ---------------- scratch (no allocation allowed) ----------------
__device__ uint32_t g_qph[BB*SS*CC/2];   // fp16 Q, token-major, pre-scaled by QS*log2e
__device__ uint32_t g_kph[BB*SS*CC/2];   // fp16 K, token-major
__device__ uint32_t g_vph[BB*SS*CC/2];   // fp16 V, d-major: [b][h][d][s]
__device__ float g_vp[BB*SS*CC];         // fp32 V (residual for mlp1)
__device__ float g_x [BB*SS*CC];         // attention output
// pre-transposed fp16 weights: set 0..2 = q/k/v, 3 = m1, 4 = m2
__device__ uint32_t g_w1t[5*256*64];     // [set][n=256][kpair=64], lo = even k
__device__ uint32_t g_w2t[5*128*128];    // [set][n=128][kpair=128]

// fp16 mma m16n8k16 row.col, fp32 accumulate
__device__ __forceinline__ void mma_f16(float* c, const uint32_t* a, uint32_t b0, uint32_t b1) {
    asm volatile(
        "mma.sync.aligned.m16n8k16.row.col.f32.f16.f16.f32 "
        "{%0,%1,%2,%3}, {%4,%5,%6,%7}, {%8,%9}, {%0,%1,%2,%3};"
        : "+f"(c[0]), "+f"(c[1]), "+f"(c[2]), "+f"(c[3])
        : "r"(a[0]), "r"(a[1]), "r"(a[2]), "r"(a[3]), "r"(b0), "r"(b1));
}
__device__ __forceinline__ float fexp2(float x) {
    float r;
    asm("ex2.approx.f32 %0, %1;" : "=f"(r) : "f"(x));
    return r;
}
__device__ __forceinline__ uint32_t cvt2h(float hi, float lo) {
    uint32_t r;
    asm("cvt.rn.f16x2.f32 %0, %1, %2;" : "=r"(r) : "f"(hi), "f"(lo));
    return r;
}
__device__ __forceinline__ float leaky(float v) { return (v > 0.f) ? v : 0.01f*v; }
__device__ __forceinline__ void cpa16(uint32_t* dst, const uint32_t* src) {
    uint32_t d = (uint32_t)__cvta_generic_to_shared(dst);
    asm volatile("cp.async.ca.shared.global [%0], [%1], 16;" :: "r"(d), "l"(src));
}
#define CP_COMMIT() asm volatile("cp.async.commit_group;" ::: "memory")
#define CP_WAIT(n)  asm volatile("cp.async.wait_group %0;" :: "n"(n) : "memory")

// ================= layouts (u32 units) =================
#define XSTRU 68
#define HSTRU 36
#define W1STRU 68
#define W2STRU 36
#define FSTR 132

// qkv smem: Xh 4352 | Hch 2304 | W1b0 4352 | W2b0 4608 | W1b1 4352 | W2b1 4608 | b/ln 768
#define QKV_SMEM_U32 (4352 + 2304 + 4352 + 4608 + 4352 + 4608 + 256 + 128 + 128 + 128 + 64 + 64)
#define QKV_SMEM_BYTES (QKV_SMEM_U32*4)
// mlp smem: Xh 4352 | Hch 2304 | 4 W bufs 17920 | Rs1f 8448 | b 384
#define MLP_SMEM_U32 (4352 + 2304 + 4352 + 4608 + 4352 + 4608 + 8448 + 256 + 128)
#define MLP_SMEM_BYTES (MLP_SMEM_U32*4)

struct ProjSet { const float *gam, *bet, *b1, *b2; };
struct QKVArgs { const float* in[3]; ProjSet ps[3]; };
struct MlpArgs { const float *b1a, *b2a, *b1b, *b2b; };
struct PrepArgs { const float* w1[5]; const float* w2[5]; };

// ================= weight prep: fp32 [k][n] -> fp16x2 transposed [n][kpair] =================
__global__ __launch_bounds__(256) void prep_weights(PrepArgs pa)
{
    const int gt = blockIdx.x*256 + threadIdx.x;
    const int stride = gridDim.x*256;
    for (int i = gt; i < 5*256*64; i += stride) {
        int s = i >> 14, r = i & 16383;
        int kk = r >> 8, n = r & 255;
        const float* w = pa.w1[s];
        g_w1t[(size_t)(s*256 + n)*64 + kk] = cvt2h(w[(2*kk+1)*HH + n], w[(2*kk)*HH + n]);
    }
    for (int i = gt; i < 5*128*128; i += stride) {
        int s = i >> 14, r = i & 16383;
        int kk = r >> 7, n = r & 127;
        const float* w = pa.w2[s];
        g_w2t[(size_t)(s*128 + n)*128 + kk] = cvt2h(w[(2*kk+1)*CC + n], w[(2*kk)*CC + n]);
    }
}

// issue one weight chunk (W1 n-range + W2 k-range) via cp.async, then commit
__device__ __forceinline__ void cp_w_chunk(int set, int hc, uint32_t* w1dst, uint32_t* w2dst, int tid)
{
    #pragma unroll
    for (int j = 0; j < 4; j++) {
        int q = tid + j*256;
        int n = q >> 4, kk4 = (q & 15)*4;
        cpa16(&w1dst[n*W1STRU + kk4], g_w1t + ((size_t)(set*256 + hc*64 + n) << 6) + kk4);
    }
    #pragma unroll
    for (int j = 0; j < 4; j++) {
        int q = tid + j*256;
        int n = q >> 3, kk4 = (q & 7)*4;
        cpa16(&w2dst[n*W2STRU + kk4], g_w2t + ((size_t)(set*128 + n) << 7) + hc*32 + kk4);
    }
    CP_COMMIT();
}

// ================= fused q/k/v projection (cp.async weight pipeline, 2 CTA/SM) =================
__global__ __launch_bounds__(256, 2)
void qkv_proj_kernel(QKVArgs a)
{
    extern __shared__ uint32_t smu[];
    uint32_t* Xh   = smu;                 // [64][68]
    uint32_t* Hch  = Xh + 4352;           // [64][36]
    uint32_t* W1b0 = Hch + 2304;
    uint32_t* W2b0 = W1b0 + 4352;
    uint32_t* W1b1 = W2b0 + 4608;
    uint32_t* W2b1 = W1b1 + 4352;
    float* Fst = (float*)W1b1;            // fp32 staging [64][132] (aliases buf1)
    float* Bs1 = (float*)(W2b1 + 4608);
    float* Bs2 = Bs1 + 256;
    float* Gs  = Bs2 + 128;
    float* Bts = Gs + 128;
    float* MUs = Bts + 128;
    float* RIs = MUs + 64;
    uint32_t* W1b[2] = {W1b0, W1b1};
    uint32_t* W2b[2] = {W2b0, W2b1};

    const int grp = blockIdx.x >> 7;
    const int bx  = blockIdx.x & 127;
    const ProjSet& p = a.ps[grp];
    const float* in = a.in[grp];

    const int tid  = threadIdx.x;
    const int wid  = tid >> 5;
    const int lane = tid & 31;
    const int g    = lane >> 2;
    const int t    = lane & 3;
    const int mrow  = (wid & 3) * 16;
    const int nhalf = (wid >> 2) * 32;

    const int gt0 = bx * 64;
    const int b   = gt0 >> 12;
    const int s0  = gt0 & (SS - 1);

    // prologue: chunk 0 -> buf0 (overlaps X load + LN)
    cp_w_chunk(grp, 0, W1b0, W2b0, tid);

    if (tid < 256) Bs1[tid] = p.b1[tid];
    if (tid < 128) { Bs2[tid] = p.b2[tid]; Gs[tid] = p.gam[tid]; Bts[tid] = p.bet[tid]; }

    // ---- load X (CHW) -> Fst fp32 (aliases buf1, safe) ----
    {
        const float* base = in + (size_t)b*CC*SS + s0;
        for (int i = tid; i < 64*CC; i += 256) {
            int c = i >> 6, tt = i & 63;
            Fst[tt*FSTR + c] = base[c*SS + tt];
        }
    }
    __syncthreads();

    // ---- LN stats: 4 threads/token ----
    {
        int token = tid >> 2, q = tid & 3;
        float s = 0.f, s2 = 0.f;
        const float* xr = &Fst[token*FSTR];
        #pragma unroll 8
        for (int i = 0; i < 32; i++) { float v = xr[q + 4*i]; s += v; s2 += v*v; }
        s  += __shfl_xor_sync(0xffffffffu, s, 1);
        s  += __shfl_xor_sync(0xffffffffu, s, 2);
        s2 += __shfl_xor_sync(0xffffffffu, s2, 1);
        s2 += __shfl_xor_sync(0xffffffffu, s2, 2);
        if (q == 0) {
            float mu = s * (1.0f/CC);
            float var = s2 * (1.0f/CC) - mu*mu;
            MUs[token] = mu;
            RIs[token] = rsqrtf(var + 1e-5f);
        }
    }
    __syncthreads();

    // ---- normalize -> Xh fp16 ----
    for (int idx = tid; idx < 64*64; idx += 256) {
        int token = idx >> 6, pr = idx & 63, c = pr*2;
        float mu = MUs[token], ri = RIs[token];
        float v0 = (Fst[token*FSTR + c]   - mu)*ri*Gs[c]   + Bts[c];
        float v1 = (Fst[token*FSTR + c+1] - mu)*ri*Gs[c+1] + Bts[c+1];
        Xh[token*XSTRU + pr] = cvt2h(v1, v0);
    }
    __syncthreads();   // Fst dead -> buf1 usable

    float acc2[2][4][4];
    #pragma unroll
    for (int n2 = 0; n2 < 2; n2++)
        #pragma unroll
        for (int jn = 0; jn < 4; jn++)
            acc2[n2][jn][0] = acc2[n2][jn][1] = acc2[n2][jn][2] = acc2[n2][jn][3] = 0.f;

    #pragma unroll 1
    for (int hc = 0; hc < 4; hc++) {
        const int pb = hc & 1;
        if (hc < 3) { cp_w_chunk(grp, hc+1, W1b[pb^1], W2b[pb^1], tid); CP_WAIT(1); }
        else        { CP_WAIT(0); }
        __syncthreads();

        // stage 1
        float acc[4][4];
        #pragma unroll
        for (int jn = 0; jn < 4; jn++)
            acc[jn][0] = acc[jn][1] = acc[jn][2] = acc[jn][3] = 0.f;
        #pragma unroll
        for (int ks = 0; ks < 8; ks++) {
            uint32_t av[4];
            const uint32_t* x0 = &Xh[(mrow+g)*XSTRU + ks*8];
            const uint32_t* x1 = x0 + 8*XSTRU;
            av[0] = x0[t]; av[1] = x1[t]; av[2] = x0[t+4]; av[3] = x1[t+4];
            #pragma unroll
            for (int jn = 0; jn < 4; jn++) {
                const uint32_t* wr = &W1b[pb][(nhalf + jn*8 + g)*W1STRU + ks*8];
                mma_f16(acc[jn], av, wr[t], wr[t+4]);
            }
        }
        #pragma unroll
        for (int jn = 0; jn < 4; jn++) {
            int col = nhalf + jn*8 + 2*t;
            float c0 = leaky(acc[jn][0] + Bs1[hc*64 + col]);
            float c1 = leaky(acc[jn][1] + Bs1[hc*64 + col + 1]);
            float c2 = leaky(acc[jn][2] + Bs1[hc*64 + col]);
            float c3 = leaky(acc[jn][3] + Bs1[hc*64 + col + 1]);
            Hch[(mrow+g)*HSTRU + (col>>1)]   = cvt2h(c1, c0);
            Hch[(mrow+g+8)*HSTRU + (col>>1)] = cvt2h(c3, c2);
        }
        __syncthreads();

        // stage 2 partial
        #pragma unroll
        for (int ks = 0; ks < 4; ks++) {
            uint32_t av[4];
            const uint32_t* h0 = &Hch[(mrow+g)*HSTRU + ks*8];
            const uint32_t* h1 = h0 + 8*HSTRU;
            av[0] = h0[t]; av[1] = h1[t]; av[2] = h0[t+4]; av[3] = h1[t+4];
            #pragma unroll
            for (int n2 = 0; n2 < 2; n2++) {
                #pragma unroll
                for (int jn = 0; jn < 4; jn++) {
                    const uint32_t* wr = &W2b[pb][(n2*64 + nhalf + jn*8 + g)*W2STRU + ks*8];
                    mma_f16(acc2[n2][jn], av, wr[t], wr[t+4]);
                }
            }
        }
        __syncthreads();
    }

    // ---- Y -> Fst fp32 ----
    #pragma unroll
    for (int n2 = 0; n2 < 2; n2++) {
        #pragma unroll
        for (int jn = 0; jn < 4; jn++) {
            int col = n2*64 + nhalf + jn*8 + 2*t;
            float* y0 = &Fst[(mrow+g)*FSTR + col];
            float* y1 = &Fst[(mrow+g+8)*FSTR + col];
            y0[0] = acc2[n2][jn][0] + Bs2[col];
            y0[1] = acc2[n2][jn][1] + Bs2[col+1];
            y1[0] = acc2[n2][jn][2] + Bs2[col];
            y1[1] = acc2[n2][jn][3] + Bs2[col+1];
        }
    }
    __syncthreads();

    // ---- grp-specific outputs ----
    if (grp < 2) {
        uint32_t* ob = (grp == 0 ? g_qph : g_kph) + (size_t)gt0*64;
        const float sc = (grp == 0) ? QS2 : 1.0f;
        for (int i = tid; i < 64*64; i += 256) {
            int tt = i >> 6, c2 = (i & 63)*2;
            float lo = Fst[tt*FSTR + c2] * sc;
            float hi = Fst[tt*FSTR + c2 + 1] * sc;
            ob[(size_t)tt*64 + (i & 63)] = cvt2h(hi, lo);
        }
    } else {
        float* ob = g_vp + (size_t)gt0*CC;
        for (int i = tid; i < 64*CC; i += 256) {
            int tt = i >> 7, c = i & 127;
            ob[i] = Fst[tt*FSTR + c];
        }
        for (int i = tid; i < 128*32; i += 256) {
            int c = i >> 5, tp = (i & 31)*2;
            float lo = Fst[tp*FSTR + c];
            float hi = Fst[(tp+1)*FSTR + c];
            size_t u32idx = ((size_t)(b*NH + (c >> 5))*DD + (c & 31))*(SS/2) + (s0 + tp)/2;
            g_vph[u32idx] = cvt2h(hi, lo);
        }
    }
}

// ================= fused MLP1+MLP2 (cp.async weight pipeline) =================
__global__ __launch_bounds__(256, 1)
void mlp_fused_kernel(MlpArgs ag, float* __restrict__ out)
{
    extern __shared__ uint32_t smu[];
    uint32_t* Xh   = smu;                 // [64][68]
    uint32_t* Hch  = Xh + 4352;           // [64][36]
    uint32_t* W1b0 = Hch + 2304;
    uint32_t* W2b0 = W1b0 + 4352;
    uint32_t* W1b1 = W2b0 + 4608;
    uint32_t* W2b1 = W1b1 + 4352;
    float* Rs1f = (float*)(W2b1 + 4608);  // [64][132] fp32
    float* Bs1  = Rs1f + 64*FSTR;
    float* Bs2  = Bs1 + 256;
    uint32_t* W1b[2] = {W1b0, W1b1};
    uint32_t* W2b[2] = {W2b0, W2b1};

    const int tid  = threadIdx.x;
    const int wid  = tid >> 5;
    const int lane = tid & 31;
    const int g    = lane >> 2;
    const int t    = lane & 3;
    const int mrow  = (wid & 3) * 16;
    const int nhalf = (wid >> 2) * 32;

    const int gt0 = blockIdx.x * 64;
    const int b   = gt0 >> 12;
    const int s0  = gt0 & (SS - 1);

    // prologue: chunk 0 (set 3) -> buf0
    cp_w_chunk(3, 0, W1b0, W2b0, tid);

    // load X (attention output) -> Xh fp16
    {
        const float* base = g_x + (size_t)gt0*CC;
        for (int idx = tid; idx < 64*64; idx += 256) {
            int token = idx >> 6, pr = idx & 63;
            float2 v = *reinterpret_cast<const float2*>(&base[token*CC + 2*pr]);
            Xh[token*XSTRU + pr] = cvt2h(v.y, v.x);
        }
    }

    #pragma unroll 1
    for (int mm = 0; mm < 2; mm++) {
        const float* b1 = mm ? ag.b1b : ag.b1a;
        const float* b2 = mm ? ag.b2b : ag.b2a;

        if (tid < 256) Bs1[tid] = b1[tid];
        if (tid < 128) Bs2[tid] = b2[tid];

        float acc2[2][4][4];
        #pragma unroll
        for (int n2 = 0; n2 < 2; n2++)
            #pragma unroll
            for (int jn = 0; jn < 4; jn++)
                acc2[n2][jn][0] = acc2[n2][jn][1] = acc2[n2][jn][2] = acc2[n2][jn][3] = 0.f;

        #pragma unroll 1
        for (int hc = 0; hc < 4; hc++) {
            const int c  = mm*4 + hc;
            const int pb = c & 1;
            if (c < 7) {
                const int nc = c + 1;
                cp_w_chunk(3 + (nc >> 2), nc & 3, W1b[pb^1], W2b[pb^1], tid);
                CP_WAIT(1);
            } else {
                CP_WAIT(0);
            }
            __syncthreads();

            // stage 1
            float acc[4][4];
            #pragma unroll
            for (int jn = 0; jn < 4; jn++)
                acc[jn][0] = acc[jn][1] = acc[jn][2] = acc[jn][3] = 0.f;
            #pragma unroll
            for (int ks = 0; ks < 8; ks++) {
                uint32_t av[4];
                const uint32_t* x0 = &Xh[(mrow+g)*XSTRU + ks*8];
                const uint32_t* x1 = x0 + 8*XSTRU;
                av[0] = x0[t]; av[1] = x1[t]; av[2] = x0[t+4]; av[3] = x1[t+4];
                #pragma unroll
                for (int jn = 0; jn < 4; jn++) {
                    const uint32_t* wr = &W1b[pb][(nhalf + jn*8 + g)*W1STRU + ks*8];
                    mma_f16(acc[jn], av, wr[t], wr[t+4]);
                }
            }
            #pragma unroll
            for (int jn = 0; jn < 4; jn++) {
                int col = nhalf + jn*8 + 2*t;
                float c0 = leaky(acc[jn][0] + Bs1[hc*64 + col]);
                float c1 = leaky(acc[jn][1] + Bs1[hc*64 + col + 1]);
                float c2 = leaky(acc[jn][2] + Bs1[hc*64 + col]);
                float c3 = leaky(acc[jn][3] + Bs1[hc*64 + col + 1]);
                Hch[(mrow+g)*HSTRU + (col>>1)]   = cvt2h(c1, c0);
                Hch[(mrow+g+8)*HSTRU + (col>>1)] = cvt2h(c3, c2);
            }
            __syncthreads();

            // stage 2 partial
            #pragma unroll
            for (int ks = 0; ks < 4; ks++) {
                uint32_t av[4];
                const uint32_t* h0 = &Hch[(mrow+g)*HSTRU + ks*8];
                const uint32_t* h1 = h0 + 8*HSTRU;
                av[0] = h0[t]; av[1] = h1[t]; av[2] = h0[t+4]; av[3] = h1[t+4];
                #pragma unroll
                for (int n2 = 0; n2 < 2; n2++) {
                    #pragma unroll
                    for (int jn = 0; jn < 4; jn++) {
                        const uint32_t* wr = &W2b[pb][(n2*64 + nhalf + jn*8 + g)*W2STRU + ks*8];
                        mma_f16(acc2[n2][jn], av, wr[t], wr[t+4]);
                    }
                }
            }
            __syncthreads();
        }

        if (mm == 0) {
            // rs1 = Y1 + b2 -> Rs1f fp32
            #pragma unroll
            for (int n2 = 0; n2 < 2; n2++) {
                #pragma unroll
                for (int jn = 0; jn < 4; jn++) {
                    int col = n2*64 + nhalf + jn*8 + 2*t;
                    float* y0 = &Rs1f[(mrow+g)*FSTR + col];
                    float* y1 = &Rs1f[(mrow+g+8)*FSTR + col];
                    y0[0] = acc2[n2][jn][0] + Bs2[col];
                    y0[1] = acc2[n2][jn][1] + Bs2[col+1];
                    y1[0] = acc2[n2][jn][2] + Bs2[col];
                    y1[1] = acc2[n2][jn][3] + Bs2[col+1];
                }
            }
            __syncthreads();
            // rs1 += vp; Xh = fp16(rs1)
            const float* rb = g_vp + (size_t)gt0*CC;
            for (int idx = tid; idx < 64*64; idx += 256) {
                int token = idx >> 6, pr = idx & 63;
                float2 vv = *reinterpret_cast<const float2*>(&rb[token*CC + 2*pr]);
                float r0 = Rs1f[token*FSTR + 2*pr]     + vv.x;
                float r1 = Rs1f[token*FSTR + 2*pr + 1] + vv.y;
                Rs1f[token*FSTR + 2*pr]     = r0;
                Rs1f[token*FSTR + 2*pr + 1] = r1;
                Xh[token*XSTRU + pr] = cvt2h(r1, r0);
            }
            __syncthreads();
        } else {
            // rs2 = rs1 + Y2 + b2 -> CHW out
            #pragma unroll
            for (int n2 = 0; n2 < 2; n2++) {
                #pragma unroll
                for (int jn = 0; jn < 4; jn++) {
                    int col = n2*64 + nhalf + jn*8 + 2*t;
                    float* y0 = &Rs1f[(mrow+g)*FSTR + col];
                    float* y1 = &Rs1f[(mrow+g+8)*FSTR + col];
                    y0[0] += acc2[n2][jn][0] + Bs2[col];
                    y0[1] += acc2[n2][jn][1] + Bs2[col+1];
                    y1[0] += acc2[n2][jn][2] + Bs2[col];
                    y1[1] += acc2[n2][jn][3] + Bs2[col+1];
                }
            }
            __syncthreads();
            float* ob = out + (size_t)b*CC*SS + s0;
            for (int i = tid; i < 64*CC; i += 256) {
                int c = i >> 6, tt = i & 63;
                ob[c*SS + tt] = Rs1f[tt*FSTR + c];
            }
        }
    }
}

// ================= fp16 mma.sync flash attention (unchanged, known-good) =================
#define KSTRU 20
#define VSTRU 36

__global__ __launch_bounds__(128, 2) void attn_mma_kernel()
{
    __shared__ uint32_t Ks[2][64*KSTRU];
    __shared__ uint32_t Vs[2][32*VSTRU];

    const int tid  = threadIdx.x;
    const int wid  = tid >> 5;
    const int lane = tid & 31;
    const int g    = lane >> 2;
    const int t    = lane & 3;
    const int h = blockIdx.y, b = blockIdx.z;
    const int q0 = blockIdx.x * 128;

    const size_t bSS = (size_t)b*SS;
    const uint32_t* kph = g_kph + bSS*64 + h*16;
    const uint32_t* vph = g_vph + ((size_t)(b*NH + h)*DD)*(SS/2);

    uint32_t qa[2][2][4];
    #pragma unroll
    for (int mf = 0; mf < 2; mf++) {
        const int r0 = q0 + wid*32 + mf*16 + g;
        const uint32_t* q0r = g_qph + (bSS + r0)*64 + h*16;
        const uint32_t* q1r = q0r + 8*64;
        #pragma unroll
        for (int ks = 0; ks < 2; ks++) {
            qa[mf][ks][0] = q0r[ks*8 + t];
            qa[mf][ks][1] = q1r[ks*8 + t];
            qa[mf][ks][2] = q0r[ks*8 + t + 4];
            qa[mf][ks][3] = q1r[ks*8 + t + 4];
        }
    }

    float O[2][4][4];
    float m[2][2], l[2][2];
    #pragma unroll
    for (int mf = 0; mf < 2; mf++) {
        #pragma unroll
        for (int j = 0; j < 4; j++)
            #pragma unroll
            for (int i = 0; i < 4; i++) O[mf][j][i] = 0.f;
        m[mf][0] = m[mf][1] = -1e30f;
        l[mf][0] = l[mf][1] = 0.f;
    }

    auto cp_tile = [&](int tile, int buf) {
        #pragma unroll
        for (int r = 0; r < 2; r++) {
            int idx = tid + r*128;
            {
                int row = idx >> 2, ch = idx & 3;
                const uint32_t* src = kph + (size_t)(tile*64 + row)*64 + ch*4;
                uint32_t d = (uint32_t)__cvta_generic_to_shared(&Ks[buf][row*KSTRU + ch*4]);
                asm volatile("cp.async.ca.shared.global [%0], [%1], 16;" :: "r"(d), "l"(src));
            }
            {
                int dd = idx >> 3, ch = idx & 7;
                const uint32_t* src = vph + (size_t)dd*(SS/2) + tile*32 + ch*4;
                uint32_t d = (uint32_t)__cvta_generic_to_shared(&Vs[buf][dd*VSTRU + ch*4]);
                asm volatile("cp.async.ca.shared.global [%0], [%1], 16;" :: "r"(d), "l"(src));
            }
        }
        asm volatile("cp.async.commit_group;" ::: "memory");
    };

    cp_tile(0, 0);

    for (int tile = 0; tile < SS/64; tile++) {
        const int buf = tile & 1;
        if (tile + 1 < SS/64) {
            cp_tile(tile + 1, buf ^ 1);
            asm volatile("cp.async.wait_group 1;" ::: "memory");
        } else {
            asm volatile("cp.async.wait_group 0;" ::: "memory");
        }
        __syncthreads();

        float s[2][8][4];
        #pragma unroll
        for (int jn = 0; jn < 8; jn++) {
            #pragma unroll
            for (int mf = 0; mf < 2; mf++)
                s[mf][jn][0] = s[mf][jn][1] = s[mf][jn][2] = s[mf][jn][3] = 0.f;
            const uint32_t* kr = &Ks[buf][(jn*8 + g)*KSTRU];
            #pragma unroll
            for (int ks = 0; ks < 2; ks++) {
                uint32_t b0 = kr[ks*8 + t];
                uint32_t b1 = kr[ks*8 + t + 4];
                mma_f16(s[0][jn], qa[0][ks], b0, b1);
                mma_f16(s[1][jn], qa[1][ks], b0, b1);
            }
        }

        float corr[2][2];
        #pragma unroll
        for (int mf = 0; mf < 2; mf++) {
            float mt0 = s[mf][0][0], mt1 = s[mf][0][2];
            #pragma unroll
            for (int jn = 0; jn < 8; jn++) {
                mt0 = fmaxf(mt0, fmaxf(s[mf][jn][0], s[mf][jn][1]));
                mt1 = fmaxf(mt1, fmaxf(s[mf][jn][2], s[mf][jn][3]));
            }
            mt0 = fmaxf(mt0, __shfl_xor_sync(0xffffffffu, mt0, 1));
            mt0 = fmaxf(mt0, __shfl_xor_sync(0xffffffffu, mt0, 2));
            mt1 = fmaxf(mt1, __shfl_xor_sync(0xffffffffu, mt1, 1));
            mt1 = fmaxf(mt1, __shfl_xor_sync(0xffffffffu, mt1, 2));
            const float mn0 = fmaxf(m[mf][0], mt0), mn1 = fmaxf(m[mf][1], mt1);
            corr[mf][0] = fexp2(m[mf][0] - mn0);
            corr[mf][1] = fexp2(m[mf][1] - mn1);
            m[mf][0] = mn0; m[mf][1] = mn1;
            float ls0 = 0.f, ls1 = 0.f;
            #pragma unroll
            for (int jn = 0; jn < 8; jn++) {
                s[mf][jn][0] = fexp2(s[mf][jn][0] - mn0); ls0 += s[mf][jn][0];
                s[mf][jn][1] = fexp2(s[mf][jn][1] - mn0); ls0 += s[mf][jn][1];
                s[mf][jn][2] = fexp2(s[mf][jn][2] - mn1); ls1 += s[mf][jn][2];
                s[mf][jn][3] = fexp2(s[mf][jn][3] - mn1); ls1 += s[mf][jn][3];
            }
            l[mf][0] = l[mf][0]*corr[mf][0] + ls0;
            l[mf][1] = l[mf][1]*corr[mf][1] + ls1;
            #pragma unroll
            for (int j = 0; j < 4; j++) {
                O[mf][j][0] *= corr[mf][0]; O[mf][j][1] *= corr[mf][0];
                O[mf][j][2] *= corr[mf][1]; O[mf][j][3] *= corr[mf][1];
            }
        }

        #pragma unroll
        for (int ks = 0; ks < 4; ks++) {
            uint32_t pa[2][4];
            #pragma unroll
            for (int mf = 0; mf < 2; mf++) {
                pa[mf][0] = cvt2h(s[mf][2*ks  ][1], s[mf][2*ks  ][0]);
                pa[mf][1] = cvt2h(s[mf][2*ks  ][3], s[mf][2*ks  ][2]);
                pa[mf][2] = cvt2h(s[mf][2*ks+1][1], s[mf][2*ks+1][0]);
                pa[mf][3] = cvt2h(s[mf][2*ks+1][3], s[mf][2*ks+1][2]);
            }
            #pragma unroll
            for (int jn = 0; jn < 4; jn++) {
                const uint32_t* vr = &Vs[buf][(jn*8 + g)*VSTRU + ks*8];
                uint32_t b0 = vr[t];
                uint32_t b1 = vr[t + 4];
                mma_f16(O[0][jn], pa[0], b0, b1);
                mma_f16(O[1][jn], pa[1], b0, b1);
            }
        }
        __syncthreads();
    }

    #pragma unroll
    for (int mf = 0; mf < 2; mf++) {
        float l0 = l[mf][0], l1 = l[mf][1];
        l0 += __shfl_xor_sync(0xffffffffu, l0, 1);
        l0 += __shfl_xor_sync(0xffffffffu, l0, 2);
        l1 += __shfl_xor_sync(0xffffffffu, l1, 1);
        l1 += __shfl_xor_sync(0xffffffffu, l1, 2);
        const float inv0 = 1.0f / l0, inv1 = 1.0f / l1;
        const int r0 = q0 + wid*32 + mf*16 + g;
        float* o0 = g_x + (bSS + r0)*CC + h*DD;
        float* o1 = o0 + 8*CC;
        #pragma unroll
        for (int jn = 0; jn < 4; jn++) {
            float2 u0 = make_float2(O[mf][jn][0]*inv0, O[mf][jn][1]*inv0);
            float2 u1 = make_float2(O[mf][jn][2]*inv1, O[mf][jn][3]*inv1);
            *reinterpret_cast<float2*>(o0 + jn*8 + 2*t) = u0;
            *reinterpret_cast<float2*>(o1 + jn*8 + 2*t) = u1;
        }
    }
}

// ---------------- launcher ----------------
extern "C" void kernel_launch(void* const* d_in, const int* in_sizes, int n_in,
                              void* d_out, int out_size)
{
    (void)in_sizes; (void)n_in; (void)out_size;
    const float* q = (const float*)d_in[0];
    const float* k = (const float*)d_in[1];
    const float* v = (const float*)d_in[2];
    float* out = (float*)d_out;

    PrepArgs pw;
    pw.w1[0] = (const float*)d_in[5];  pw.w2[0] = (const float*)d_in[7];
    pw.w1[1] = (const float*)d_in[11]; pw.w2[1] = (const float*)d_in[13];
    pw.w1[2] = (const float*)d_in[17]; pw.w2[2] = (const float*)d_in[19];
    pw.w1[3] = (const float*)d_in[21]; pw.w2[3] = (const float*)d_in[23];
    pw.w1[4] = (const float*)d_in[25]; pw.w2[4] = (const float*)d_in[27];

    QKVArgs qa;
    qa.in[0] = q; qa.in[1] = k; qa.in[2] = v;
    qa.ps[0] = ProjSet{ (const float*)d_in[3],  (const float*)d_in[4],
                        (const float*)d_in[6],  (const float*)d_in[8] };
    qa.ps[1] = ProjSet{ (const float*)d_in[9],  (const float*)d_in[10],
                        (const float*)d_in[12], (const float*)d_in[14] };
    qa.ps[2] = ProjSet{ (const float*)d_in[15], (const float*)d_in[16],
                        (const float*)d_in[18], (const float*)d_in[20] };

    MlpArgs ma;
    ma.b1a = (const float*)d_in[22]; ma.b2a = (const float*)d_in[24];
    ma.b1b = (const float*)d_in[26]; ma.b2b = (const float*)d_in[28];

    cudaFuncSetAttribute(qkv_proj_kernel,
                         cudaFuncAttributeMaxDynamicSharedMemorySize, QKV_SMEM_BYTES);
    cudaFuncSetAttribute(mlp_fused_kernel,
                         cudaFuncAttributeMaxDynamicSharedMemorySize, MLP_SMEM_BYTES);

    // weight prep: fp32 -> fp16 transposed
    prep_weights<<<160, 256>>>(pw);

    // fused q/k/v projections -> g_qph/g_kph/(g_vp + g_vph)
    qkv_proj_kernel<<<384, 256, QKV_SMEM_BYTES>>>(qa);

    // fp16 flash attention -> g_x
    attn_mma_kernel<<<dim3(SS/128, NH, BB), 128>>>();

    // fused rs1+rs2 -> out (CHW)
    mlp_fused_kernel<<<128, 256, MLP_SMEM_BYTES>>>(ma, out);
}

// round 13
// speedup vs baseline: 1.1285x; 1.1285x over previous
#include <cuda_runtime.h>
#include <math.h>
#include <stdint.h>

#define BB 2
#define CC 128
#define HH 256      // 2*C
#define SS 4096     // 64*64 tokens
#define NH 4
#define DD 32       // head dim

#define QS 0.1767766952966369f   // 1/sqrt(32)
#define QS2 (QS * 1.4426950408889634f)   // fold log2(e) for ex2-domain softmax

// ---------------- scratch (no allocation allowed) ----------------
__device__ uint32_t g_qph[BB*SS*CC/2];   // fp16 Q, token-major, pre-scaled by QS*log2e
__device__ uint32_t g_kph[BB*SS*CC/2];   // fp16 K, token-major
__device__ uint32_t g_vph[BB*SS*CC/2];   // fp16 V, d-major: [b][h][d][s]
__device__ float g_vp[BB*SS*CC];         // fp32 V (residual for mlp1)
__device__ float g_x [BB*SS*CC];         // attention output

// fp16 mma m16n8k16 row.col, fp32 accumulate
__device__ __forceinline__ void mma_f16(float* c, const uint32_t* a, uint32_t b0, uint32_t b1) {
    asm volatile(
        "mma.sync.aligned.m16n8k16.row.col.f32.f16.f16.f32 "
        "{%0,%1,%2,%3}, {%4,%5,%6,%7}, {%8,%9}, {%0,%1,%2,%3};"
        : "+f"(c[0]), "+f"(c[1]), "+f"(c[2]), "+f"(c[3])
        : "r"(a[0]), "r"(a[1]), "r"(a[2]), "r"(a[3]), "r"(b0), "r"(b1));
}
__device__ __forceinline__ float fexp2(float x) {
    float r;
    asm("ex2.approx.f32 %0, %1;" : "=f"(r) : "f"(x));
    return r;
}
__device__ __forceinline__ uint32_t h2exp2(uint32_t x) {
    uint32_t r;
    asm("ex2.approx.f16x2 %0, %1;" : "=r"(r) : "r"(x));
    return r;
}
// pack {hi, lo} floats -> f16x2 (lo in low half)
__device__ __forceinline__ uint32_t cvt2h(float hi, float lo) {
    uint32_t r;
    asm("cvt.rn.f16x2.f32 %0, %1, %2;" : "=r"(r) : "f"(hi), "f"(lo));
    return r;
}
__device__ __forceinline__ float leaky(float v) { return (v > 0.f) ? v : 0.01f*v; }

// ================= fp16 projection layouts (u32 units) =================
#define XSTRU 68    // X/H-row pairs: 64 pairs + pad4
#define HSTRU 36    // H chunk: 32 pairs + pad4
#define W1STRU 68   // W1h [n=64][kpair=64]+pad
#define W2STRU 36   // W2h [n=128][kpair=32]+pad
#define FSTR 132    // fp32 staging stride

#define QKV_SMEM_U32 (4352 + 2304 + 4352 + 4608 + 256 + 128 + 128 + 128 + 64 + 64)
#define QKV_SMEM_BYTES (QKV_SMEM_U32*4)
#define MLP_SMEM_U32 (4352 + 2304 + 4352 + 4608 + 8448 + 256 + 128)
#define MLP_SMEM_BYTES (MLP_SMEM_U32*4)

struct ProjSet { const float *gam, *bet, *w1, *b1, *w2, *b2; };
struct QKVArgs { const float* in[3]; ProjSet ps[3]; };
struct MlpArgs { const float *w1a, *b1a, *w2a, *b2a, *w1b, *b1b, *w2b, *b2b; };

// ================= fused q/k/v projection (round-11 known-good, fp16 GEMMs) =================
__global__ __launch_bounds__(256, 2)
void qkv_proj_kernel(QKVArgs a)
{
    extern __shared__ uint32_t smu[];
    uint32_t* Xh  = smu;                      // [64][68]
    uint32_t* Hch = Xh + 64*XSTRU;            // [64][36]
    uint32_t* W1h = Hch + 64*HSTRU;           // [64][68]
    uint32_t* W2h = W1h + 64*W1STRU;          // [128][36]
    float* Fst = (float*)W1h;                 // fp32 staging [64][132] (aliases W1h+W2h)
    float* Bs1 = (float*)(W2h + 128*W2STRU);
    float* Bs2 = Bs1 + 256;
    float* Gs  = Bs2 + 128;
    float* Bts = Gs + 128;
    float* MUs = Bts + 128;
    float* RIs = MUs + 64;

    const int grp = blockIdx.x >> 7;
    const int bx  = blockIdx.x & 127;
    const ProjSet& p = a.ps[grp];
    const float* in = a.in[grp];
    const float* w1 = p.w1;
    const float* w2 = p.w2;

    const int tid  = threadIdx.x;
    const int wid  = tid >> 5;
    const int lane = tid & 31;
    const int g    = lane >> 2;
    const int t    = lane & 3;
    const int mrow  = (wid & 3) * 16;
    const int nhalf = (wid >> 2) * 32;

    const int gt0 = bx * 64;
    const int b   = gt0 >> 12;
    const int s0  = gt0 & (SS - 1);

    if (tid < 256) Bs1[tid] = p.b1[tid];
    if (tid < 128) { Bs2[tid] = p.b2[tid]; Gs[tid] = p.gam[tid]; Bts[tid] = p.bet[tid]; }

    {
        const float* base = in + (size_t)b*CC*SS + s0;
        for (int i = tid; i < 64*CC; i += 256) {
            int c = i >> 6, tt = i & 63;
            Fst[tt*FSTR + c] = base[c*SS + tt];
        }
    }
    __syncthreads();

    {
        int token = tid >> 2, q = tid & 3;
        float s = 0.f, s2 = 0.f;
        const float* xr = &Fst[token*FSTR];
        #pragma unroll 8
        for (int i = 0; i < 32; i++) { float v = xr[q + 4*i]; s += v; s2 += v*v; }
        s  += __shfl_xor_sync(0xffffffffu, s, 1);
        s  += __shfl_xor_sync(0xffffffffu, s, 2);
        s2 += __shfl_xor_sync(0xffffffffu, s2, 1);
        s2 += __shfl_xor_sync(0xffffffffu, s2, 2);
        if (q == 0) {
            float mu = s * (1.0f/CC);
            float var = s2 * (1.0f/CC) - mu*mu;
            MUs[token] = mu;
            RIs[token] = rsqrtf(var + 1e-5f);
        }
    }
    __syncthreads();

    for (int idx = tid; idx < 64*64; idx += 256) {
        int token = idx >> 6, pr = idx & 63, c = pr*2;
        float mu = MUs[token], ri = RIs[token];
        float v0 = (Fst[token*FSTR + c]   - mu)*ri*Gs[c]   + Bts[c];
        float v1 = (Fst[token*FSTR + c+1] - mu)*ri*Gs[c+1] + Bts[c+1];
        Xh[token*XSTRU + pr] = cvt2h(v1, v0);
    }
    __syncthreads();

    float acc2[2][4][4];
    #pragma unroll
    for (int n2 = 0; n2 < 2; n2++)
        #pragma unroll
        for (int jn = 0; jn < 4; jn++)
            acc2[n2][jn][0] = acc2[n2][jn][1] = acc2[n2][jn][2] = acc2[n2][jn][3] = 0.f;

    #pragma unroll 1
    for (int hc = 0; hc < 4; hc++) {
        #pragma unroll
        for (int j = 0; j < 4; j++) {
            int idx = tid + j*256;
            int n = idx & 63, kk4 = (idx >> 6)*4;
            uint32_t u[4];
            #pragma unroll
            for (int z = 0; z < 4; z++) {
                int kk = kk4 + z;
                float e = w1[(size_t)(2*kk)*HH + hc*64 + n];
                float o = w1[(size_t)(2*kk+1)*HH + hc*64 + n];
                u[z] = cvt2h(o, e);
            }
            *reinterpret_cast<uint4*>(&W1h[n*W1STRU + kk4]) = make_uint4(u[0],u[1],u[2],u[3]);
        }
        __syncthreads();

        float acc[4][4];
        #pragma unroll
        for (int jn = 0; jn < 4; jn++)
            acc[jn][0] = acc[jn][1] = acc[jn][2] = acc[jn][3] = 0.f;
        #pragma unroll
        for (int ks = 0; ks < 8; ks++) {
            uint32_t av[4];
            const uint32_t* x0 = &Xh[(mrow+g)*XSTRU + ks*8];
            const uint32_t* x1 = x0 + 8*XSTRU;
            av[0] = x0[t]; av[1] = x1[t]; av[2] = x0[t+4]; av[3] = x1[t+4];
            #pragma unroll
            for (int jn = 0; jn < 4; jn++) {
                const uint32_t* wr = &W1h[(nhalf + jn*8 + g)*W1STRU + ks*8];
                mma_f16(acc[jn], av, wr[t], wr[t+4]);
            }
        }
        #pragma unroll
        for (int jn = 0; jn < 4; jn++) {
            int col = nhalf + jn*8 + 2*t;
            float c0 = leaky(acc[jn][0] + Bs1[hc*64 + col]);
            float c1 = leaky(acc[jn][1] + Bs1[hc*64 + col + 1]);
            float c2 = leaky(acc[jn][2] + Bs1[hc*64 + col]);
            float c3 = leaky(acc[jn][3] + Bs1[hc*64 + col + 1]);
            Hch[(mrow+g)*HSTRU + (col>>1)]   = cvt2h(c1, c0);
            Hch[(mrow+g+8)*HSTRU + (col>>1)] = cvt2h(c3, c2);
        }
        __syncthreads();

        #pragma unroll
        for (int j = 0; j < 4; j++) {
            int idx = tid + j*256;
            int n = idx & 127, kk4 = (idx >> 7)*4;
            uint32_t u[4];
            #pragma unroll
            for (int z = 0; z < 4; z++) {
                int kk = kk4 + z;
                float e = w2[(size_t)(hc*64 + 2*kk)*CC + n];
                float o = w2[(size_t)(hc*64 + 2*kk+1)*CC + n];
                u[z] = cvt2h(o, e);
            }
            *reinterpret_cast<uint4*>(&W2h[n*W2STRU + kk4]) = make_uint4(u[0],u[1],u[2],u[3]);
        }
        __syncthreads();

        #pragma unroll
        for (int ks = 0; ks < 4; ks++) {
            uint32_t av[4];
            const uint32_t* h0 = &Hch[(mrow+g)*HSTRU + ks*8];
            const uint32_t* h1 = h0 + 8*HSTRU;
            av[0] = h0[t]; av[1] = h1[t]; av[2] = h0[t+4]; av[3] = h1[t+4];
            #pragma unroll
            for (int n2 = 0; n2 < 2; n2++) {
                #pragma unroll
                for (int jn = 0; jn < 4; jn++) {
                    const uint32_t* wr = &W2h[(n2*64 + nhalf + jn*8 + g)*W2STRU + ks*8];
                    mma_f16(acc2[n2][jn], av, wr[t], wr[t+4]);
                }
            }
        }
        __syncthreads();
    }

    #pragma unroll
    for (int n2 = 0; n2 < 2; n2++) {
        #pragma unroll
        for (int jn = 0; jn < 4; jn++) {
            int col = n2*64 + nhalf + jn*8 + 2*t;
            float* y0 = &Fst[(mrow+g)*FSTR + col];
            float* y1 = &Fst[(mrow+g+8)*FSTR + col];
            y0[0] = acc2[n2][jn][0] + Bs2[col];
            y0[1] = acc2[n2][jn][1] + Bs2[col+1];
            y1[0] = acc2[n2][jn][2] + Bs2[col];
            y1[1] = acc2[n2][jn][3] + Bs2[col+1];
        }
    }
    __syncthreads();

    if (grp < 2) {
        uint32_t* ob = (grp == 0 ? g_qph : g_kph) + (size_t)gt0*64;
        const float sc = (grp == 0) ? QS2 : 1.0f;
        for (int i = tid; i < 64*64; i += 256) {
            int tt = i >> 6, c2 = (i & 63)*2;
            float lo = Fst[tt*FSTR + c2] * sc;
            float hi = Fst[tt*FSTR + c2 + 1] * sc;
            ob[(size_t)tt*64 + (i & 63)] = cvt2h(hi, lo);
        }
    } else {
        float* ob = g_vp + (size_t)gt0*CC;
        for (int i = tid; i < 64*CC; i += 256) {
            int tt = i >> 7, c = i & 127;
            ob[i] = Fst[tt*FSTR + c];
        }
        for (int i = tid; i < 128*32; i += 256) {
            int c = i >> 5, tp = (i & 31)*2;
            float lo = Fst[tp*FSTR + c];
            float hi = Fst[(tp+1)*FSTR + c];
            size_t u32idx = ((size_t)(b*NH + (c >> 5))*DD + (c & 31))*(SS/2) + (s0 + tp)/2;
            g_vph[u32idx] = cvt2h(hi, lo);
        }
    }
}

// ================= fused MLP1+MLP2 (round-11 known-good, register-prefetched weights) =================
__global__ __launch_bounds__(256, 1)
void mlp_fused_kernel(MlpArgs ag, float* __restrict__ out)
{
    extern __shared__ uint32_t smu[];
    uint32_t* Xh   = smu;                     // [64][68]
    uint32_t* Hch  = Xh + 64*XSTRU;           // [64][36]
    uint32_t* W1h  = Hch + 64*HSTRU;          // [64][68]
    uint32_t* W2h  = W1h + 64*W1STRU;         // [128][36]
    float* Rs1f = (float*)(W2h + 128*W2STRU); // [64][132] fp32
    float* Bs1  = Rs1f + 64*FSTR;
    float* Bs2  = Bs1 + 256;

    const int tid  = threadIdx.x;
    const int wid  = tid >> 5;
    const int lane = tid & 31;
    const int g    = lane >> 2;
    const int t    = lane & 3;
    const int mrow  = (wid & 3) * 16;
    const int nhalf = (wid >> 2) * 32;

    const int gt0 = blockIdx.x * 64;
    const int b   = gt0 >> 12;
    const int s0  = gt0 & (SS - 1);

    float wreg[32];
    #pragma unroll
    for (int j = 0; j < 4; j++) {
        int idx = tid + j*256;
        int n = idx & 63, kk4 = (idx >> 6)*4;
        #pragma unroll
        for (int z = 0; z < 4; z++) {
            int kk = kk4 + z;
            wreg[j*8 + z*2 + 0] = ag.w1a[(size_t)(2*kk)*HH + n];
            wreg[j*8 + z*2 + 1] = ag.w1a[(size_t)(2*kk+1)*HH + n];
        }
    }

    {
        const float* base = g_x + (size_t)gt0*CC;
        for (int idx = tid; idx < 64*64; idx += 256) {
            int token = idx >> 6, pr = idx & 63;
            float2 v = *reinterpret_cast<const float2*>(&base[token*CC + 2*pr]);
            Xh[token*XSTRU + pr] = cvt2h(v.y, v.x);
        }
    }

    #pragma unroll 1
    for (int mm = 0; mm < 2; mm++) {
        const float* w1 = mm ? ag.w1b : ag.w1a;
        const float* b1 = mm ? ag.b1b : ag.b1a;
        const float* w2 = mm ? ag.w2b : ag.w2a;
        const float* b2 = mm ? ag.b2b : ag.b2a;
        const float* w1_next = mm ? nullptr : ag.w1b;

        if (tid < 256) Bs1[tid] = b1[tid];
        if (tid < 128) Bs2[tid] = b2[tid];

        float acc2[2][4][4];
        #pragma unroll
        for (int n2 = 0; n2 < 2; n2++)
            #pragma unroll
            for (int jn = 0; jn < 4; jn++)
                acc2[n2][jn][0] = acc2[n2][jn][1] = acc2[n2][jn][2] = acc2[n2][jn][3] = 0.f;

        #pragma unroll 1
        for (int hc = 0; hc < 4; hc++) {
            #pragma unroll
            for (int j = 0; j < 4; j++) {
                int idx = tid + j*256;
                int n = idx & 63, kk4 = (idx >> 6)*4;
                uint32_t u[4];
                #pragma unroll
                for (int z = 0; z < 4; z++)
                    u[z] = cvt2h(wreg[j*8 + z*2 + 1], wreg[j*8 + z*2]);
                *reinterpret_cast<uint4*>(&W1h[n*W1STRU + kk4]) = make_uint4(u[0],u[1],u[2],u[3]);
            }
            #pragma unroll
            for (int j = 0; j < 4; j++) {
                int idx = tid + j*256;
                int n = idx & 127, kk4 = (idx >> 7)*4;
                #pragma unroll
                for (int z = 0; z < 4; z++) {
                    int kk = kk4 + z;
                    wreg[j*8 + z*2 + 0] = w2[(size_t)(hc*64 + 2*kk)*CC + n];
                    wreg[j*8 + z*2 + 1] = w2[(size_t)(hc*64 + 2*kk+1)*CC + n];
                }
            }
            __syncthreads();

            float acc[4][4];
            #pragma unroll
            for (int jn = 0; jn < 4; jn++)
                acc[jn][0] = acc[jn][1] = acc[jn][2] = acc[jn][3] = 0.f;
            #pragma unroll
            for (int ks = 0; ks < 8; ks++) {
                uint32_t av[4];
                const uint32_t* x0 = &Xh[(mrow+g)*XSTRU + ks*8];
                const uint32_t* x1 = x0 + 8*XSTRU;
                av[0] = x0[t]; av[1] = x1[t]; av[2] = x0[t+4]; av[3] = x1[t+4];
                #pragma unroll
                for (int jn = 0; jn < 4; jn++) {
                    const uint32_t* wr = &W1h[(nhalf + jn*8 + g)*W1STRU + ks*8];
                    mma_f16(acc[jn], av, wr[t], wr[t+4]);
                }
            }
            #pragma unroll
            for (int jn = 0; jn < 4; jn++) {
                int col = nhalf + jn*8 + 2*t;
                float c0 = leaky(acc[jn][0] + Bs1[hc*64 + col]);
                float c1 = leaky(acc[jn][1] + Bs1[hc*64 + col + 1]);
                float c2 = leaky(acc[jn][2] + Bs1[hc*64 + col]);
                float c3 = leaky(acc[jn][3] + Bs1[hc*64 + col + 1]);
                Hch[(mrow+g)*HSTRU + (col>>1)]   = cvt2h(c1, c0);
                Hch[(mrow+g+8)*HSTRU + (col>>1)] = cvt2h(c3, c2);
            }
            __syncthreads();

            #pragma unroll
            for (int j = 0; j < 4; j++) {
                int idx = tid + j*256;
                int n = idx & 127, kk4 = (idx >> 7)*4;
                uint32_t u[4];
                #pragma unroll
                for (int z = 0; z < 4; z++)
                    u[z] = cvt2h(wreg[j*8 + z*2 + 1], wreg[j*8 + z*2]);
                *reinterpret_cast<uint4*>(&W2h[n*W2STRU + kk4]) = make_uint4(u[0],u[1],u[2],u[3]);
            }
            if (hc < 3) {
                #pragma unroll
                for (int j = 0; j < 4; j++) {
                    int idx = tid + j*256;
                    int n = idx & 63, kk4 = (idx >> 6)*4;
                    #pragma unroll
                    for (int z = 0; z < 4; z++) {
                        int kk = kk4 + z;
                        wreg[j*8 + z*2 + 0] = w1[(size_t)(2*kk)*HH + (hc+1)*64 + n];
                        wreg[j*8 + z*2 + 1] = w1[(size_t)(2*kk+1)*HH + (hc+1)*64 + n];
                    }
                }
            } else if (w1_next) {
                #pragma unroll
                for (int j = 0; j < 4; j++) {
                    int idx = tid + j*256;
                    int n = idx & 63, kk4 = (idx >> 6)*4;
                    #pragma unroll
                    for (int z = 0; z < 4; z++) {
                        int kk = kk4 + z;
                        wreg[j*8 + z*2 + 0] = w1_next[(size_t)(2*kk)*HH + n];
                        wreg[j*8 + z*2 + 1] = w1_next[(size_t)(2*kk+1)*HH + n];
                    }
                }
            }
            __syncthreads();

            #pragma unroll
            for (int ks = 0; ks < 4; ks++) {
                uint32_t av[4];
                const uint32_t* h0 = &Hch[(mrow+g)*HSTRU + ks*8];
                const uint32_t* h1 = h0 + 8*HSTRU;
                av[0] = h0[t]; av[1] = h1[t]; av[2] = h0[t+4]; av[3] = h1[t+4];
                #pragma unroll
                for (int n2 = 0; n2 < 2; n2++) {
                    #pragma unroll
                    for (int jn = 0; jn < 4; jn++) {
                        const uint32_t* wr = &W2h[(n2*64 + nhalf + jn*8 + g)*W2STRU + ks*8];
                        mma_f16(acc2[n2][jn], av, wr[t], wr[t+4]);
                    }
                }
            }
            __syncthreads();
        }

        if (mm == 0) {
            #pragma unroll
            for (int n2 = 0; n2 < 2; n2++) {
                #pragma unroll
                for (int jn = 0; jn < 4; jn++) {
                    int col = n2*64 + nhalf + jn*8 + 2*t;
                    float* y0 = &Rs1f[(mrow+g)*FSTR + col];
                    float* y1 = &Rs1f[(mrow+g+8)*FSTR + col];
                    y0[0] = acc2[n2][jn][0] + Bs2[col];
                    y0[1] = acc2[n2][jn][1] + Bs2[col+1];
                    y1[0] = acc2[n2][jn][2] + Bs2[col];
                    y1[1] = acc2[n2][jn][3] + Bs2[col+1];
                }
            }
            __syncthreads();
            const float* rb = g_vp + (size_t)gt0*CC;
            for (int idx = tid; idx < 64*64; idx += 256) {
                int token = idx >> 6, pr = idx & 63;
                float2 vv = *reinterpret_cast<const float2*>(&rb[token*CC + 2*pr]);
                float r0 = Rs1f[token*FSTR + 2*pr]     + vv.x;
                float r1 = Rs1f[token*FSTR + 2*pr + 1] + vv.y;
                Rs1f[token*FSTR + 2*pr]     = r0;
                Rs1f[token*FSTR + 2*pr + 1] = r1;
                Xh[token*XSTRU + pr] = cvt2h(r1, r0);
            }
            __syncthreads();
        } else {
            #pragma unroll
            for (int n2 = 0; n2 < 2; n2++) {
                #pragma unroll
                for (int jn = 0; jn < 4; jn++) {
                    int col = n2*64 + nhalf + jn*8 + 2*t;
                    float* y0 = &Rs1f[(mrow+g)*FSTR + col];
                    float* y1 = &Rs1f[(mrow+g+8)*FSTR + col];
                    y0[0] += acc2[n2][jn][0] + Bs2[col];
                    y0[1] += acc2[n2][jn][1] + Bs2[col+1];
                    y1[0] += acc2[n2][jn][2] + Bs2[col];
                    y1[1] += acc2[n2][jn][3] + Bs2[col+1];
                }
            }
            __syncthreads();
            float* ob = out + (size_t)b*CC*SS + s0;
            for (int i = tid; i < 64*CC; i += 256) {
                int c = i >> 6, tt = i & 63;
                ob[c*SS + tt] = Rs1f[tt*FSTR + c];
            }
        }
    }
}

// ================= fp16 flash attention: f16x2 exp + ones-column l =================
#define KSTRU 20
#define VSTRU 36

__global__ __launch_bounds__(128, 2) void attn_mma_kernel()
{
    __shared__ uint32_t Ks[2][64*KSTRU];
    __shared__ uint32_t Vs[2][40*VSTRU];   // rows 0-31 = V d-major; row 32 = ones; 33-39 = zero

    const int tid  = threadIdx.x;
    const int wid  = tid >> 5;
    const int lane = tid & 31;
    const int g    = lane >> 2;
    const int t    = lane & 3;
    const int h = blockIdx.y, b = blockIdx.z;
    const int q0 = blockIdx.x * 128;

    const size_t bSS = (size_t)b*SS;
    const uint32_t* kph = g_kph + bSS*64 + h*16;
    const uint32_t* vph = g_vph + ((size_t)(b*NH + h)*DD)*(SS/2);

    // init ones/zero rows (static across tiles)
    for (int i = tid; i < 2*8*VSTRU; i += 128) {
        int bufi = (i >= 8*VSTRU);
        int r = (i / VSTRU) & 7, cidx = i % VSTRU;
        Vs[bufi][(32+r)*VSTRU + cidx] = (r == 0) ? 0x3C003C00u : 0u;
    }

    uint32_t qa[2][2][4];
    #pragma unroll
    for (int mf = 0; mf < 2; mf++) {
        const int r0 = q0 + wid*32 + mf*16 + g;
        const uint32_t* q0r = g_qph + (bSS + r0)*64 + h*16;
        const uint32_t* q1r = q0r + 8*64;
        #pragma unroll
        for (int ks = 0; ks < 2; ks++) {
            qa[mf][ks][0] = q0r[ks*8 + t];
            qa[mf][ks][1] = q1r[ks*8 + t];
            qa[mf][ks][2] = q0r[ks*8 + t + 4];
            qa[mf][ks][3] = q1r[ks*8 + t + 4];
        }
    }

    float O[2][5][4];     // jn=4 holds l in col 32 (and zeros)
    float m[2][2];
    #pragma unroll
    for (int mf = 0; mf < 2; mf++) {
        #pragma unroll
        for (int j = 0; j < 5; j++)
            #pragma unroll
            for (int i = 0; i < 4; i++) O[mf][j][i] = 0.f;
        m[mf][0] = m[mf][1] = -1e30f;
    }

    auto cp_tile = [&](int tile, int buf) {
        #pragma unroll
        for (int r = 0; r < 2; r++) {
            int idx = tid + r*128;
            {
                int row = idx >> 2, ch = idx & 3;
                const uint32_t* src = kph + (size_t)(tile*64 + row)*64 + ch*4;
                uint32_t d = (uint32_t)__cvta_generic_to_shared(&Ks[buf][row*KSTRU + ch*4]);
                asm volatile("cp.async.ca.shared.global [%0], [%1], 16;" :: "r"(d), "l"(src));
            }
            {
                int dd = idx >> 3, ch = idx & 7;
                const uint32_t* src = vph + (size_t)dd*(SS/2) + tile*32 + ch*4;
                uint32_t d = (uint32_t)__cvta_generic_to_shared(&Vs[buf][dd*VSTRU + ch*4]);
                asm volatile("cp.async.ca.shared.global [%0], [%1], 16;" :: "r"(d), "l"(src));
            }
        }
        asm volatile("cp.async.commit_group;" ::: "memory");
    };

    cp_tile(0, 0);

    for (int tile = 0; tile < SS/64; tile++) {
        const int buf = tile & 1;
        if (tile + 1 < SS/64) {
            cp_tile(tile + 1, buf ^ 1);
            asm volatile("cp.async.wait_group 1;" ::: "memory");
        } else {
            asm volatile("cp.async.wait_group 0;" ::: "memory");
        }
        __syncthreads();

        // ---- S = Q @ K^T ----
        float s[2][8][4];
        #pragma unroll
        for (int jn = 0; jn < 8; jn++) {
            #pragma unroll
            for (int mf = 0; mf < 2; mf++)
                s[mf][jn][0] = s[mf][jn][1] = s[mf][jn][2] = s[mf][jn][3] = 0.f;
            const uint32_t* kr = &Ks[buf][(jn*8 + g)*KSTRU];
            #pragma unroll
            for (int ks = 0; ks < 2; ks++) {
                uint32_t b0 = kr[ks*8 + t];
                uint32_t b1 = kr[ks*8 + t + 4];
                mma_f16(s[0][jn], qa[0][ks], b0, b1);
                mma_f16(s[1][jn], qa[1][ks], b0, b1);
            }
        }

        // ---- softmax: fp16x2 exp, P stored as packed fp16 A-frags ----
        uint32_t ph[2][8][2];
        #pragma unroll
        for (int mf = 0; mf < 2; mf++) {
            float mt0 = s[mf][0][0], mt1 = s[mf][0][2];
            #pragma unroll
            for (int jn = 0; jn < 8; jn++) {
                mt0 = fmaxf(mt0, fmaxf(s[mf][jn][0], s[mf][jn][1]));
                mt1 = fmaxf(mt1, fmaxf(s[mf][jn][2], s[mf][jn][3]));
            }
            mt0 = fmaxf(mt0, __shfl_xor_sync(0xffffffffu, mt0, 1));
            mt0 = fmaxf(mt0, __shfl_xor_sync(0xffffffffu, mt0, 2));
            mt1 = fmaxf(mt1, __shfl_xor_sync(0xffffffffu, mt1, 1));
            mt1 = fmaxf(mt1, __shfl_xor_sync(0xffffffffu, mt1, 2));
            const float mn0 = fmaxf(m[mf][0], mt0), mn1 = fmaxf(m[mf][1], mt1);
            const float corr0 = fexp2(m[mf][0] - mn0);
            const float corr1 = fexp2(m[mf][1] - mn1);
            m[mf][0] = mn0; m[mf][1] = mn1;
            #pragma unroll
            for (int jn = 0; jn < 8; jn++) {
                ph[mf][jn][0] = h2exp2(cvt2h(s[mf][jn][1] - mn0, s[mf][jn][0] - mn0));
                ph[mf][jn][1] = h2exp2(cvt2h(s[mf][jn][3] - mn1, s[mf][jn][2] - mn1));
            }
            #pragma unroll
            for (int j = 0; j < 5; j++) {
                O[mf][j][0] *= corr0; O[mf][j][1] *= corr0;
                O[mf][j][2] *= corr1; O[mf][j][3] *= corr1;
            }
        }

        // ---- O|l += P @ [V ; 1] ----
        #pragma unroll
        for (int ks = 0; ks < 4; ks++) {
            uint32_t pa[2][4];
            #pragma unroll
            for (int mf = 0; mf < 2; mf++) {
                pa[mf][0] = ph[mf][2*ks  ][0];
                pa[mf][1] = ph[mf][2*ks  ][1];
                pa[mf][2] = ph[mf][2*ks+1][0];
                pa[mf][3] = ph[mf][2*ks+1][1];
            }
            #pragma unroll
            for (int jn = 0; jn < 5; jn++) {
                const uint32_t* vr = &Vs[buf][(jn*8 + g)*VSTRU + ks*8];
                uint32_t b0 = vr[t];
                uint32_t b1 = vr[t + 4];
                mma_f16(O[0][jn], pa[0], b0, b1);
                mma_f16(O[1][jn], pa[1], b0, b1);
            }
        }
        __syncthreads();
    }

    // ---- epilogue: l = O[.][4][0/2] from t=0 lane of quad ----
    #pragma unroll
    for (int mf = 0; mf < 2; mf++) {
        const int srcT0 = lane & ~3;
        float l0 = __shfl_sync(0xffffffffu, O[mf][4][0], srcT0);
        float l1 = __shfl_sync(0xffffffffu, O[mf][4][2], srcT0);
        const float inv0 = 1.0f / l0, inv1 = 1.0f / l1;
        const int r0 = q0 + wid*32 + mf*16 + g;
        float* o0 = g_x + (bSS + r0)*CC + h*DD;
        float* o1 = o0 + 8*CC;
        #pragma unroll
        for (int jn = 0; jn < 4; jn++) {
            float2 u0 = make_float2(O[mf][jn][0]*inv0, O[mf][jn][1]*inv0);
            float2 u1 = make_float2(O[mf][jn][2]*inv1, O[mf][jn][3]*inv1);
            *reinterpret_cast<float2*>(o0 + jn*8 + 2*t) = u0;
            *reinterpret_cast<float2*>(o1 + jn*8 + 2*t) = u1;
        }
    }
}

// ---------------- launcher ----------------
extern "C" void kernel_launch(void* const* d_in, const int* in_sizes, int n_in,
                              void* d_out, int out_size)
{
    (void)in_sizes; (void)n_in; (void)out_size;
    const float* q = (const float*)d_in[0];
    const float* k = (const float*)d_in[1];
    const float* v = (const float*)d_in[2];
    float* out = (float*)d_out;

    QKVArgs qa;
    qa.in[0] = q; qa.in[1] = k; qa.in[2] = v;
    qa.ps[0] = ProjSet{ (const float*)d_in[3], (const float*)d_in[4],
                        (const float*)d_in[5], (const float*)d_in[6],
                        (const float*)d_in[7], (const float*)d_in[8] };
    qa.ps[1] = ProjSet{ (const float*)d_in[9], (const float*)d_in[10],
                        (const float*)d_in[11], (const float*)d_in[12],
                        (const float*)d_in[13], (const float*)d_in[14] };
    qa.ps[2] = ProjSet{ (const float*)d_in[15], (const float*)d_in[16],
                        (const float*)d_in[17], (const float*)d_in[18],
                        (const float*)d_in[19], (const float*)d_in[20] };

    MlpArgs ma;
    ma.w1a = (const float*)d_in[21]; ma.b1a = (const float*)d_in[22];
    ma.w2a = (const float*)d_in[23]; ma.b2a = (const float*)d_in[24];
    ma.w1b = (const float*)d_in[25]; ma.b1b = (const float*)d_in[26];
    ma.w2b = (const float*)d_in[27]; ma.b2b = (const float*)d_in[28];

    cudaFuncSetAttribute(qkv_proj_kernel,
                         cudaFuncAttributeMaxDynamicSharedMemorySize, QKV_SMEM_BYTES);
    cudaFuncSetAttribute(mlp_fused_kernel,
                         cudaFuncAttributeMaxDynamicSharedMemorySize, MLP_SMEM_BYTES);

    // fused q/k/v projections -> g_qph/g_kph/(g_vp + g_vph)
    qkv_proj_kernel<<<384, 256, QKV_SMEM_BYTES>>>(qa);

    // fp16 flash attention -> g_x
    attn_mma_kernel<<<dim3(SS/128, NH, BB), 128>>>();

    // fused rs1+rs2 -> out (CHW)
    mlp_fused_kernel<<<128, 256, MLP_SMEM_BYTES>>>(ma, out);
}